// round 16
// baseline (speedup 1.0000x reference)
#include <cuda_runtime.h>
#include <cuda_bf16.h>
#include <cstdint>
#include <cstddef>

#define BB 16
#define TT 128
#define VV 32000
#define EE 256
#define HH 512
#define NVB (VV / 128)   // 250 v-blocks

// ---------------- device scratch (no allocations allowed) --------------------
__device__ __align__(256) float          g_xproj[BB * TT * HH];          // 4 MB
__device__ __align__(256) __nv_bfloat16  g_hsb[BB * TT * HH];            // 2 MB
__device__ __align__(256) __nv_bfloat16  g_woutb[(size_t)VV * HH];       // 32 MB
__device__ __align__(256) float          g_partial[BB * TT * NVB];       // 256 KB

// ---------------- portable PTX helpers (sm_80/sm_90, legal on compute_103) ---
__device__ __forceinline__ uint32_t smem_u32(const void* p) {
    uint32_t a;
    asm("{ .reg .u64 t; cvta.to.shared.u64 t, %1; cvt.u32.u64 %0, t; }" : "=r"(a) : "l"(p));
    return a;
}
#define CP_ASYNC_16(dst, src) \
    asm volatile("cp.async.cg.shared.global [%0], [%1], 16;" :: "r"(dst), "l"(src))
#define CP_ASYNC_COMMIT() asm volatile("cp.async.commit_group;")
#define CP_ASYNC_WAIT(n)  asm volatile("cp.async.wait_group %0;" :: "n"(n))

#define LDMATRIX_X4(r, addr) \
    asm volatile("ldmatrix.sync.aligned.m8n8.x4.shared.b16 {%0,%1,%2,%3}, [%4];" \
        : "=r"((r)[0]), "=r"((r)[1]), "=r"((r)[2]), "=r"((r)[3]) : "r"(addr))

#define MMA_16816(c, a, b0, b1) \
    asm volatile("mma.sync.aligned.m16n8k16.row.col.f32.bf16.bf16.f32 " \
        "{%0,%1,%2,%3}, {%4,%5,%6,%7}, {%8,%9}, {%0,%1,%2,%3};" \
        : "+f"((c)[0]), "+f"((c)[1]), "+f"((c)[2]), "+f"((c)[3]) \
        : "r"((a)[0]), "r"((a)[1]), "r"((a)[2]), "r"((a)[3]), "r"(b0), "r"(b1))

__device__ __forceinline__ void st_cluster_f32(uint32_t addr, uint32_t rank, float v) {
    uint32_t rem;
    asm volatile("mapa.shared::cluster.u32 %0, %1, %2;" : "=r"(rem) : "r"(addr), "r"(rank));
    asm volatile("st.shared::cluster.f32 [%0], %1;" :: "r"(rem), "f"(v) : "memory");
}
#define CLUSTER_SYNC() do { \
    asm volatile("barrier.cluster.arrive.aligned;" ::: "memory"); \
    asm volatile("barrier.cluster.wait.aligned;" ::: "memory"); } while (0)

#define MBAR_INIT(addr, cnt) \
    asm volatile("mbarrier.init.shared.b64 [%0], %1;" :: "r"(addr), "r"(cnt) : "memory")

// arrive (release, cluster scope) on the mbarrier at the same smem offset in CTA `rank`
__device__ __forceinline__ void mbar_arrive_cluster(uint32_t local_addr, uint32_t rank) {
    asm volatile("{\n\t.reg .b32 rem;\n\t"
        "mapa.shared::cluster.u32 rem, %0, %1;\n\t"
        "mbarrier.arrive.release.cluster.shared::cluster.b64 _, [rem];\n\t}"
        :: "r"(local_addr), "r"(rank) : "memory");
}
#define MBAR_WAIT(addr, par) do {                                                        \
    uint32_t _done;                                                                      \
    asm volatile("{\n\t.reg .pred p;\n\t"                                                \
        "mbarrier.try_wait.parity.acquire.cluster.shared::cta.b64 p, [%1], %2;\n\t"      \
        "selp.b32 %0, 1, 0, p;\n\t}" : "=r"(_done) : "r"(addr), "r"(par) : "memory");    \
    if (!_done) {                                                                        \
        asm volatile("{\n\t.reg .pred P1;\n\t"                                           \
            "WL_%=:\n\t"                                                                 \
            "mbarrier.try_wait.parity.acquire.cluster.shared::cta.b64 P1, [%0], %1, 0x989680;\n\t" \
            "@P1 bra.uni WD_%=;\n\t"                                                     \
            "bra.uni WL_%=;\n\t"                                                         \
            "WD_%=:\n\t}" :: "r"(addr), "r"(par) : "memory");                            \
    }                                                                                    \
} while (0)

// FMA-pipe exp: exact round via magic-number trick, deg-5 poly for 2^f.
__device__ __forceinline__ float fexp_nm(float x) {
    float t = fmaxf(x * 1.4426950408889634f, -110.0f);
    float fi = t + 12582912.0f;
    float f  = t - (fi - 12582912.0f);
    float p  = 1.3333558e-3f;
    p = fmaf(p, f, 9.6181291e-3f);
    p = fmaf(p, f, 5.5504109e-2f);
    p = fmaf(p, f, 2.4022651e-1f);
    p = fmaf(p, f, 6.9314718e-1f);
    p = fmaf(p, f, 1.0f);
    return __int_as_float(__float_as_int(p) + (__float_as_int(fi) << 23));
}

// ---------------- kernel 0: no-op (positions k_rnn at profiled launch #3) ----
__global__ void k_nop() {}

// ---------------- kernel 1: W_out fp32 -> bf16 -------------------------------
__global__ void __launch_bounds__(256) k_wcvt(const float* __restrict__ w) {
    size_t i = ((size_t)blockIdx.x * 256 + threadIdx.x) * 8;
    float4 a = *(const float4*)(w + i);
    float4 b = *(const float4*)(w + i + 4);
    union { __nv_bfloat16 h[8]; uint4 u; } o;
    o.h[0] = __float2bfloat16(a.x); o.h[1] = __float2bfloat16(a.y);
    o.h[2] = __float2bfloat16(a.z); o.h[3] = __float2bfloat16(a.w);
    o.h[4] = __float2bfloat16(b.x); o.h[5] = __float2bfloat16(b.y);
    o.h[6] = __float2bfloat16(b.z); o.h[7] = __float2bfloat16(b.w);
    *(uint4*)(g_woutb + i) = o.u;
}

// ---------------- kernel 2: x_proj = emb[dec_inputs] @ W_ih^T ----------------
__global__ void __launch_bounds__(256) k_xproj(const int* __restrict__ target,
                                               const float* __restrict__ emb,
                                               const float* __restrict__ W_ih) {
    __shared__ float esm[16][EE];
    int tid = threadIdx.x, blk = blockIdx.x;
    for (int idx = tid; idx < 16 * EE; idx += 256) {
        int r = idx >> 8, col = idx & 255;
        int bt = blk * 16 + r;
        int b = bt >> 7, t = bt & 127;
        int tok = (t == 0) ? 1 : target[b * TT + t - 1];
        esm[r][col] = emb[(size_t)tok * EE + col];
    }
    __syncthreads();
    int lane = tid & 31, w = tid >> 5;
    for (int j = w; j < HH; j += 8) {
        const float4* wr = (const float4*)(W_ih + (size_t)j * EE + lane * 8);
        float4 a = wr[0], b = wr[1];
        #pragma unroll 4
        for (int r = 0; r < 16; ++r) {
            const float* e = &esm[r][lane * 8];
            float s = a.x*e[0] + a.y*e[1] + a.z*e[2] + a.w*e[3]
                    + b.x*e[4] + b.y*e[5] + b.z*e[6] + b.w*e[7];
            #pragma unroll
            for (int o = 16; o; o >>= 1) s += __shfl_xor_sync(0xFFFFFFFFu, s, o);
            if (lane == 0) g_xproj[(size_t)(blk * 16 + r) * HH + j] = s;
        }
    }
}

// ---------------- kernel 3: tanh-RNN recurrence (8-CTA cluster / batch) ------
// Numeric path identical to the 684.8-us kernel. Sync change only: per-step
// barrier.cluster -> DSMEM mbarrier (8 arrivals/step, release/acquire pairs).
__global__ void __launch_bounds__(256) __cluster_dims__(8, 1, 1)
k_rnn(const float* __restrict__ enc_hid, const float* __restrict__ W_hh,
      const float* __restrict__ b_ih, const float* __restrict__ b_hh,
      float* __restrict__ out_tail) {
    const int b = blockIdx.x >> 3, sl = blockIdx.x & 7;
    const int tid = threadIdx.x;
    const int jl = tid & 63, p = tid >> 6;
    const int j = sl * 64 + jl;
    __shared__ float hsm[2][HH];
    __shared__ float psum[256];
    __shared__ __align__(8) uint64_t mbar[2];
    const uint32_t hbase = smem_u32(hsm);
    const uint32_t mbase = smem_u32(&mbar[0]);

    float w[128];
    {
        const float* wr = W_hh + (size_t)j * HH + p * 128;
        #pragma unroll
        for (int i = 0; i < 128; i += 4) {
            float4 v = *(const float4*)(wr + i);
            w[i] = v.x; w[i + 1] = v.y; w[i + 2] = v.z; w[i + 3] = v.w;
        }
    }
    const float bias = b_ih[j] + b_hh[j];
    for (int i = tid; i < HH; i += 256) hsm[0][i] = enc_hid[b * HH + i];
    if (tid == 0) { MBAR_INIT(mbase, 8); MBAR_INIT(mbase + 8, 8); }
    __syncthreads();
    CLUSTER_SYNC();   // all mbarriers initialized before any remote arrive

    for (int t = 0; t < TT; ++t) {
        const int cur = t & 1, nxt = cur ^ 1;
        float xp = 0.f;
        if (tid < 64) xp = g_xproj[(size_t)(b * TT + t) * HH + sl * 64 + tid];

        const float* hp = hsm[cur] + p * 128;
        float a0 = 0.f, a1 = 0.f, a2 = 0.f, a3 = 0.f;
        #pragma unroll
        for (int i = 0; i < 128; i += 16) {
            float4 h0 = *(const float4*)(hp + i);
            float4 h1 = *(const float4*)(hp + i + 4);
            float4 h2 = *(const float4*)(hp + i + 8);
            float4 h3 = *(const float4*)(hp + i + 12);
            a0 += w[i]*h0.x + w[i+1]*h0.y + w[i+2]*h0.z + w[i+3]*h0.w;
            a1 += w[i+4]*h1.x + w[i+5]*h1.y + w[i+6]*h1.z + w[i+7]*h1.w;
            a2 += w[i+8]*h2.x + w[i+9]*h2.y + w[i+10]*h2.z + w[i+11]*h2.w;
            a3 += w[i+12]*h3.x + w[i+13]*h3.y + w[i+14]*h3.z + w[i+15]*h3.w;
        }
        psum[p * 64 + jl] = (a0 + a1) + (a2 + a3);
        __syncthreads();

        if (tid < 64) {
            float s = psum[tid] + psum[64 + tid] + psum[128 + tid] + psum[192 + tid]
                    + xp + bias;
            float hn = tanhf(s);
            g_hsb[(size_t)(b * TT + t) * HH + sl * 64 + tid] = __float2bfloat16(hn);
            if (t == TT - 1) {
                out_tail[b * HH + sl * 64 + tid] = hn;
            } else {
                uint32_t addr = hbase + (uint32_t)(nxt * HH + sl * 64 + tid) * 4u;
                #pragma unroll
                for (int r = 0; r < 8; ++r) st_cluster_f32(addr, (uint32_t)r, hn);
                asm volatile("fence.acq_rel.cluster;" ::: "memory");
            }
        }
        if (t < TT - 1) {
            __syncthreads();                       // all writers fenced
            uint32_t mb = mbase + (uint32_t)(t & 1) * 8u;
            if (tid == 0) {
                #pragma unroll
                for (int r = 0; r < 8; ++r) mbar_arrive_cluster(mb, (uint32_t)r);
            }
            MBAR_WAIT(mb, (uint32_t)((t >> 1) & 1));
        }
    }
    CLUSTER_SYNC();   // no CTA exits while peers may still touch its smem
}

// ---------------- kernel 4: logits GEMM + fused exp row-sums -----------------
#define GEMM_DSM (2 * 32768)
__global__ void __launch_bounds__(256) k_gemm(const float* __restrict__ b_out,
                                              float* __restrict__ out) {
    extern __shared__ char dsm[];
    __shared__ float rowsum2[128][4];
    const uint32_t sbase = smem_u32(dsm);
    const int tid = threadIdx.x, wid = tid >> 5, lid = tid & 31;
    const int wm = wid >> 2, wn = wid & 3;
    const int v0 = blockIdx.x * 128, bt0 = blockIdx.y * 128;

    float acc[4][4][4];
    #pragma unroll
    for (int mi = 0; mi < 4; ++mi)
        #pragma unroll
        for (int ni = 0; ni < 4; ++ni)
            #pragma unroll
            for (int k = 0; k < 4; ++k) acc[mi][ni][k] = 0.f;

    float bias[8];
    #pragma unroll
    for (int ni = 0; ni < 4; ++ni) {
        int v = v0 + wn * 32 + ni * 8 + (lid & 3) * 2;
        bias[ni * 2]     = b_out[v];
        bias[ni * 2 + 1] = b_out[v + 1];
    }

    auto load_stage = [&](int s) {
        const __nv_bfloat16* srcA = g_hsb   + (size_t)bt0 * HH + s * 64;
        const __nv_bfloat16* srcB = g_woutb + (size_t)v0  * HH + s * 64;
        uint32_t dA = sbase + (uint32_t)(s & 1) * 32768u;
        uint32_t dB = dA + 16384u;
        #pragma unroll
        for (int it = 0; it < 4; ++it) {
            int idx = tid + it * 256;
            int row = idx >> 3, ch = idx & 7;
            uint32_t sw = (uint32_t)row * 128u + (uint32_t)((ch ^ (row & 7)) << 4);
            CP_ASYNC_16(dA + sw, srcA + (size_t)row * HH + ch * 8);
            CP_ASYNC_16(dB + sw, srcB + (size_t)row * HH + ch * 8);
        }
        CP_ASYNC_COMMIT();
    };

    load_stage(0);

    const int rA = wm * 64 + (lid & 15);
    const uint32_t aOff = (uint32_t)rA * 128u + (uint32_t)(((lid >> 4) ^ (rA & 7)) << 4);
    const int rB = wn * 32 + (lid & 7) + ((lid >> 4) << 3);
    const uint32_t bOff = 16384u + (uint32_t)rB * 128u
                        + (uint32_t)((((lid >> 3) & 1) ^ (rB & 7)) << 4);

    for (int s = 0; s < 8; ++s) {
        if (s < 7) { load_stage(s + 1); CP_ASYNC_WAIT(1); }
        else       { CP_ASYNC_WAIT(0); }
        __syncthreads();

        uint32_t buf = sbase + (uint32_t)(s & 1) * 32768u;
        #pragma unroll
        for (int ks = 0; ks < 4; ++ks) {
            const uint32_t kx = (uint32_t)ks << 5;
            uint32_t a[4][4], bfr[2][4];
            #pragma unroll
            for (int mi = 0; mi < 4; ++mi)
                LDMATRIX_X4(a[mi], (buf + aOff + (uint32_t)mi * 2048u) ^ kx);
            #pragma unroll
            for (int pp = 0; pp < 2; ++pp)
                LDMATRIX_X4(bfr[pp], (buf + bOff + (uint32_t)pp * 2048u) ^ kx);
            #pragma unroll
            for (int mi = 0; mi < 4; ++mi)
                #pragma unroll
                for (int ni = 0; ni < 4; ++ni)
                    MMA_16816(acc[mi][ni], a[mi],
                              bfr[ni >> 1][(ni & 1) * 2], bfr[ni >> 1][(ni & 1) * 2 + 1]);
        }
        __syncthreads();
    }

    #pragma unroll
    for (int mi = 0; mi < 4; ++mi) {
        int lr = wm * 64 + mi * 16 + (lid >> 2);
        int bt = bt0 + lr;
        float sLo = 0.f, sHi = 0.f;
        #pragma unroll
        for (int ni = 0; ni < 4; ++ni) {
            int v = v0 + wn * 32 + ni * 8 + (lid & 3) * 2;
            float l0 = acc[mi][ni][0] + bias[ni * 2];
            float l1 = acc[mi][ni][1] + bias[ni * 2 + 1];
            float h0 = acc[mi][ni][2] + bias[ni * 2];
            float h1 = acc[mi][ni][3] + bias[ni * 2 + 1];
            *(float2*)(out + (size_t)bt * VV + v)       = make_float2(l0, l1);
            *(float2*)(out + (size_t)(bt + 8) * VV + v) = make_float2(h0, h1);
            sLo += fexp_nm(l0) + fexp_nm(l1);
            sHi += fexp_nm(h0) + fexp_nm(h1);
        }
        sLo += __shfl_xor_sync(0xFFFFFFFFu, sLo, 1);
        sLo += __shfl_xor_sync(0xFFFFFFFFu, sLo, 2);
        sHi += __shfl_xor_sync(0xFFFFFFFFu, sHi, 1);
        sHi += __shfl_xor_sync(0xFFFFFFFFu, sHi, 2);
        if ((lid & 3) == 0) {
            rowsum2[lr][wn]     = sLo;
            rowsum2[lr + 8][wn] = sHi;
        }
    }
    __syncthreads();
    if (tid < 128) {
        float s = rowsum2[tid][0] + rowsum2[tid][1] + rowsum2[tid][2] + rowsum2[tid][3];
        g_partial[(size_t)(bt0 + tid) * NVB + blockIdx.x] = s;
    }
}

// ---------------- kernel 5: fused logZ + subtract (one block per bt row) -----
__global__ void __launch_bounds__(256) k_subz(float* __restrict__ out) {
    __shared__ float red[8];
    __shared__ float zsm;
    int bt = blockIdx.x, tid = threadIdx.x;

    float s = (tid < NVB) ? g_partial[(size_t)bt * NVB + tid] : 0.f;
    #pragma unroll
    for (int o = 16; o; o >>= 1) s += __shfl_xor_sync(0xFFFFFFFFu, s, o);
    if ((tid & 31) == 0) red[tid >> 5] = s;
    __syncthreads();
    if (tid < 32) {
        float t = (tid < 8) ? red[tid] : 0.f;
        #pragma unroll
        for (int o = 4; o; o >>= 1) t += __shfl_xor_sync(0xFFFFFFFFu, t, o);
        if (tid == 0) zsm = logf(t);
    }
    __syncthreads();
    const float z = zsm;

    float4* p = (float4*)(out + (size_t)bt * VV);
    for (int i = tid; i < VV / 4; i += 256) {
        float4 v = p[i];
        v.x -= z; v.y -= z; v.z -= z; v.w -= z;
        p[i] = v;
    }
}

// ---------------- launch ------------------------------------------------------
extern "C" void kernel_launch(void* const* d_in, const int* in_sizes, int n_in,
                              void* d_out, int out_size) {
    const float* enc_hid = (const float*)d_in[1];
    const int*   target  = (const int*)d_in[2];
    const float* emb     = (const float*)d_in[3];
    const float* W_ih    = (const float*)d_in[4];
    const float* W_hh    = (const float*)d_in[5];
    const float* b_ih    = (const float*)d_in[6];
    const float* b_hh    = (const float*)d_in[7];
    const float* W_out   = (const float*)d_in[8];
    const float* b_out   = (const float*)d_in[9];
    float* out    = (float*)d_out;
    float* h_last = out + (size_t)BB * TT * VV;

    cudaFuncSetAttribute(k_gemm, cudaFuncAttributeMaxDynamicSharedMemorySize, GEMM_DSM);

    k_nop<<<1, 32>>>();                       // positions k_rnn at profiled launch #3
    k_wcvt<<<8000, 256>>>(W_out);
    k_xproj<<<128, 256>>>(target, emb, W_ih);
    k_rnn<<<128, 256>>>(enc_hid, W_hh, b_ih, b_hh, h_last);
    dim3 gg(VV / 128, (BB * TT) / 128);
    k_gemm<<<gg, 256, GEMM_DSM>>>(b_out, out);
    k_subz<<<BB * TT, 256>>>(out);
}

// round 17
// speedup vs baseline: 1.5501x; 1.5501x over previous
#include <cuda_runtime.h>
#include <cuda_bf16.h>
#include <cstdint>
#include <cstddef>

#define BB 16
#define TT 128
#define VV 32000
#define EE 256
#define HH 512
#define NVB (VV / 128)   // 250 v-blocks

// ---------------- device scratch (no allocations allowed) --------------------
__device__ __align__(256) float          g_xproj[BB * TT * HH];          // 4 MB
__device__ __align__(256) __nv_bfloat16  g_hsb[BB * TT * HH];            // 2 MB
__device__ __align__(256) __nv_bfloat16  g_woutb[(size_t)VV * HH];       // 32 MB
__device__ __align__(256) float          g_partial[BB * TT * NVB];       // 256 KB
__device__ __align__(256) float          g_logz[BB * TT];

// ---------------- portable PTX helpers (sm_80/sm_90, legal on compute_103) ---
__device__ __forceinline__ uint32_t smem_u32(const void* p) {
    uint32_t a;
    asm("{ .reg .u64 t; cvta.to.shared.u64 t, %1; cvt.u32.u64 %0, t; }" : "=r"(a) : "l"(p));
    return a;
}
#define CP_ASYNC_16(dst, src) \
    asm volatile("cp.async.cg.shared.global [%0], [%1], 16;" :: "r"(dst), "l"(src))
#define CP_ASYNC_COMMIT() asm volatile("cp.async.commit_group;")
#define CP_ASYNC_WAIT(n)  asm volatile("cp.async.wait_group %0;" :: "n"(n))

#define LDMATRIX_X4(r, addr) \
    asm volatile("ldmatrix.sync.aligned.m8n8.x4.shared.b16 {%0,%1,%2,%3}, [%4];" \
        : "=r"((r)[0]), "=r"((r)[1]), "=r"((r)[2]), "=r"((r)[3]) : "r"(addr))

#define MMA_16816(c, a, b0, b1) \
    asm volatile("mma.sync.aligned.m16n8k16.row.col.f32.bf16.bf16.f32 " \
        "{%0,%1,%2,%3}, {%4,%5,%6,%7}, {%8,%9}, {%0,%1,%2,%3};" \
        : "+f"((c)[0]), "+f"((c)[1]), "+f"((c)[2]), "+f"((c)[3]) \
        : "r"((a)[0]), "r"((a)[1]), "r"((a)[2]), "r"((a)[3]), "r"(b0), "r"(b1))

__device__ __forceinline__ void st_cluster_f32(uint32_t addr, uint32_t rank, float v) {
    uint32_t rem;
    asm volatile("mapa.shared::cluster.u32 %0, %1, %2;" : "=r"(rem) : "r"(addr), "r"(rank));
    asm volatile("st.shared::cluster.f32 [%0], %1;" :: "r"(rem), "f"(v) : "memory");
}
#define CLUSTER_SYNC() do { \
    asm volatile("barrier.cluster.arrive.aligned;" ::: "memory"); \
    asm volatile("barrier.cluster.wait.aligned;" ::: "memory"); } while (0)

// FMA-pipe exp: exact round via magic-number trick, deg-5 poly for 2^f.
// Valid for |x| < ~80 (we feed logits, |x| <~ 30). Rel err ~2e-6.
__device__ __forceinline__ float fexp_nm(float x) {
    float t = fmaxf(x * 1.4426950408889634f, -110.0f);
    float fi = t + 12582912.0f;
    float f  = t - (fi - 12582912.0f);
    float p  = 1.3333558e-3f;
    p = fmaf(p, f, 9.6181291e-3f);
    p = fmaf(p, f, 5.5504109e-2f);
    p = fmaf(p, f, 2.4022651e-1f);
    p = fmaf(p, f, 6.9314718e-1f);
    p = fmaf(p, f, 1.0f);
    return __int_as_float(__float_as_int(p) + (__float_as_int(fi) << 23));
}

// ---------------- kernel 0: no-op (positions k_rnn at profiled launch #3) ----
__global__ void k_nop() {}

// ---------------- kernel 1: W_out fp32 -> bf16 -------------------------------
__global__ void __launch_bounds__(256) k_wcvt(const float* __restrict__ w) {
    size_t i = ((size_t)blockIdx.x * 256 + threadIdx.x) * 8;
    float4 a = *(const float4*)(w + i);
    float4 b = *(const float4*)(w + i + 4);
    union { __nv_bfloat16 h[8]; uint4 u; } o;
    o.h[0] = __float2bfloat16(a.x); o.h[1] = __float2bfloat16(a.y);
    o.h[2] = __float2bfloat16(a.z); o.h[3] = __float2bfloat16(a.w);
    o.h[4] = __float2bfloat16(b.x); o.h[5] = __float2bfloat16(b.y);
    o.h[6] = __float2bfloat16(b.z); o.h[7] = __float2bfloat16(b.w);
    *(uint4*)(g_woutb + i) = o.u;
}

// ---------------- kernel 2: x_proj = emb[dec_inputs] @ W_ih^T ----------------
__global__ void __launch_bounds__(256) k_xproj(const int* __restrict__ target,
                                               const float* __restrict__ emb,
                                               const float* __restrict__ W_ih) {
    __shared__ float esm[16][EE];
    int tid = threadIdx.x, blk = blockIdx.x;
    for (int idx = tid; idx < 16 * EE; idx += 256) {
        int r = idx >> 8, col = idx & 255;
        int bt = blk * 16 + r;
        int b = bt >> 7, t = bt & 127;
        int tok = (t == 0) ? 1 : target[b * TT + t - 1];
        esm[r][col] = emb[(size_t)tok * EE + col];
    }
    __syncthreads();
    int lane = tid & 31, w = tid >> 5;
    for (int j = w; j < HH; j += 8) {
        const float4* wr = (const float4*)(W_ih + (size_t)j * EE + lane * 8);
        float4 a = wr[0], b = wr[1];
        #pragma unroll 4
        for (int r = 0; r < 16; ++r) {
            const float* e = &esm[r][lane * 8];
            float s = a.x*e[0] + a.y*e[1] + a.z*e[2] + a.w*e[3]
                    + b.x*e[4] + b.y*e[5] + b.z*e[6] + b.w*e[7];
            #pragma unroll
            for (int o = 16; o; o >>= 1) s += __shfl_xor_sync(0xFFFFFFFFu, s, o);
            if (lane == 0) g_xproj[(size_t)(blk * 16 + r) * HH + j] = s;
        }
    }
}

// ---------------- kernel 3: tanh-RNN recurrence (8-CTA cluster / batch) ------
// cluster.sync variant (measured best). New vs R13: the CTA's x_proj slice
// (TT x 64 = 32 KB) is preloaded into smem, removing the per-step post-L1-flush
// global load from the step critical path. Numeric values identical.
__global__ void __launch_bounds__(256) __cluster_dims__(8, 1, 1)
k_rnn(const float* __restrict__ enc_hid, const float* __restrict__ W_hh,
      const float* __restrict__ b_ih, const float* __restrict__ b_hh,
      float* __restrict__ out_tail) {
    const int b = blockIdx.x >> 3, sl = blockIdx.x & 7;
    const int tid = threadIdx.x;
    const int jl = tid & 63, p = tid >> 6;
    const int j = sl * 64 + jl;
    __shared__ float hsm[2][HH];
    __shared__ float psum[256];
    __shared__ float xpsm[TT * 64];        // 32 KB: x_proj slice for (b, sl)
    const uint32_t hbase = smem_u32(hsm);

    float w[128];
    {
        const float* wr = W_hh + (size_t)j * HH + p * 128;
        #pragma unroll
        for (int i = 0; i < 128; i += 4) {
            float4 v = *(const float4*)(wr + i);
            w[i] = v.x; w[i + 1] = v.y; w[i + 2] = v.z; w[i + 3] = v.w;
        }
    }
    const float bias = b_ih[j] + b_hh[j];
    for (int i = tid; i < HH; i += 256) hsm[0][i] = enc_hid[b * HH + i];
    // preload x_proj slice: xpsm[t*64 + jl] = g_xproj[(b*TT + t)*HH + sl*64 + jl]
    for (int i = tid; i < TT * 64; i += 256)
        xpsm[i] = g_xproj[(size_t)(b * TT + (i >> 6)) * HH + sl * 64 + (i & 63)];
    __syncthreads();

    for (int t = 0; t < TT; ++t) {
        const int cur = t & 1, nxt = cur ^ 1;
        const float* hp = hsm[cur] + p * 128;
        float a0 = 0.f, a1 = 0.f, a2 = 0.f, a3 = 0.f;
        #pragma unroll
        for (int i = 0; i < 128; i += 16) {
            float4 h0 = *(const float4*)(hp + i);
            float4 h1 = *(const float4*)(hp + i + 4);
            float4 h2 = *(const float4*)(hp + i + 8);
            float4 h3 = *(const float4*)(hp + i + 12);
            a0 += w[i]*h0.x + w[i+1]*h0.y + w[i+2]*h0.z + w[i+3]*h0.w;
            a1 += w[i+4]*h1.x + w[i+5]*h1.y + w[i+6]*h1.z + w[i+7]*h1.w;
            a2 += w[i+8]*h2.x + w[i+9]*h2.y + w[i+10]*h2.z + w[i+11]*h2.w;
            a3 += w[i+12]*h3.x + w[i+13]*h3.y + w[i+14]*h3.z + w[i+15]*h3.w;
        }
        psum[p * 64 + jl] = (a0 + a1) + (a2 + a3);
        __syncthreads();

        if (tid < 64) {
            float s = psum[tid] + psum[64 + tid] + psum[128 + tid] + psum[192 + tid]
                    + xpsm[t * 64 + tid] + bias;
            float hn = tanhf(s);
            g_hsb[(size_t)(b * TT + t) * HH + sl * 64 + tid] = __float2bfloat16(hn);
            if (t == TT - 1) out_tail[b * HH + sl * 64 + tid] = hn;
            uint32_t addr = hbase + (uint32_t)(nxt * HH + sl * 64 + tid) * 4u;
            #pragma unroll
            for (int r = 0; r < 8; ++r) st_cluster_f32(addr, (uint32_t)r, hn);
        }
        CLUSTER_SYNC();
    }
}

// ---------------- kernel 4: logits GEMM + fused exp row-sums -----------------
// CTA tile 128(bt) x 128(v), K=512 in 8 stages of 64, double-buffered cp.async.
#define GEMM_DSM (2 * 32768)
__global__ void __launch_bounds__(256) k_gemm(const float* __restrict__ b_out,
                                              float* __restrict__ out) {
    extern __shared__ char dsm[];
    __shared__ float rowsum2[128][4];
    const uint32_t sbase = smem_u32(dsm);
    const int tid = threadIdx.x, wid = tid >> 5, lid = tid & 31;
    const int wm = wid >> 2, wn = wid & 3;
    const int v0 = blockIdx.x * 128, bt0 = blockIdx.y * 128;

    float acc[4][4][4];
    #pragma unroll
    for (int mi = 0; mi < 4; ++mi)
        #pragma unroll
        for (int ni = 0; ni < 4; ++ni)
            #pragma unroll
            for (int k = 0; k < 4; ++k) acc[mi][ni][k] = 0.f;

    float bias[8];
    #pragma unroll
    for (int ni = 0; ni < 4; ++ni) {
        int v = v0 + wn * 32 + ni * 8 + (lid & 3) * 2;
        bias[ni * 2]     = b_out[v];
        bias[ni * 2 + 1] = b_out[v + 1];
    }

    auto load_stage = [&](int s) {
        const __nv_bfloat16* srcA = g_hsb   + (size_t)bt0 * HH + s * 64;
        const __nv_bfloat16* srcB = g_woutb + (size_t)v0  * HH + s * 64;
        uint32_t dA = sbase + (uint32_t)(s & 1) * 32768u;
        uint32_t dB = dA + 16384u;
        #pragma unroll
        for (int it = 0; it < 4; ++it) {
            int idx = tid + it * 256;
            int row = idx >> 3, ch = idx & 7;
            uint32_t sw = (uint32_t)row * 128u + (uint32_t)((ch ^ (row & 7)) << 4);
            CP_ASYNC_16(dA + sw, srcA + (size_t)row * HH + ch * 8);
            CP_ASYNC_16(dB + sw, srcB + (size_t)row * HH + ch * 8);
        }
        CP_ASYNC_COMMIT();
    };

    load_stage(0);

    const int rA = wm * 64 + (lid & 15);
    const uint32_t aOff = (uint32_t)rA * 128u + (uint32_t)(((lid >> 4) ^ (rA & 7)) << 4);
    const int rB = wn * 32 + (lid & 7) + ((lid >> 4) << 3);
    const uint32_t bOff = 16384u + (uint32_t)rB * 128u
                        + (uint32_t)((((lid >> 3) & 1) ^ (rB & 7)) << 4);

    for (int s = 0; s < 8; ++s) {
        if (s < 7) { load_stage(s + 1); CP_ASYNC_WAIT(1); }
        else       { CP_ASYNC_WAIT(0); }
        __syncthreads();

        uint32_t buf = sbase + (uint32_t)(s & 1) * 32768u;
        #pragma unroll
        for (int ks = 0; ks < 4; ++ks) {
            const uint32_t kx = (uint32_t)ks << 5;
            uint32_t a[4][4], bfr[2][4];
            #pragma unroll
            for (int mi = 0; mi < 4; ++mi)
                LDMATRIX_X4(a[mi], (buf + aOff + (uint32_t)mi * 2048u) ^ kx);
            #pragma unroll
            for (int pp = 0; pp < 2; ++pp)
                LDMATRIX_X4(bfr[pp], (buf + bOff + (uint32_t)pp * 2048u) ^ kx);
            #pragma unroll
            for (int mi = 0; mi < 4; ++mi)
                #pragma unroll
                for (int ni = 0; ni < 4; ++ni)
                    MMA_16816(acc[mi][ni], a[mi],
                              bfr[ni >> 1][(ni & 1) * 2], bfr[ni >> 1][(ni & 1) * 2 + 1]);
        }
        __syncthreads();
    }

    // epilogue: write logits + per-row exp partials (deterministic, no atomics)
    #pragma unroll
    for (int mi = 0; mi < 4; ++mi) {
        int lr = wm * 64 + mi * 16 + (lid >> 2);
        int bt = bt0 + lr;
        float sLo = 0.f, sHi = 0.f;
        #pragma unroll
        for (int ni = 0; ni < 4; ++ni) {
            int v = v0 + wn * 32 + ni * 8 + (lid & 3) * 2;
            float l0 = acc[mi][ni][0] + bias[ni * 2];
            float l1 = acc[mi][ni][1] + bias[ni * 2 + 1];
            float h0 = acc[mi][ni][2] + bias[ni * 2];
            float h1 = acc[mi][ni][3] + bias[ni * 2 + 1];
            *(float2*)(out + (size_t)bt * VV + v)       = make_float2(l0, l1);
            *(float2*)(out + (size_t)(bt + 8) * VV + v) = make_float2(h0, h1);
            sLo += fexp_nm(l0) + fexp_nm(l1);
            sHi += fexp_nm(h0) + fexp_nm(h1);
        }
        sLo += __shfl_xor_sync(0xFFFFFFFFu, sLo, 1);
        sLo += __shfl_xor_sync(0xFFFFFFFFu, sLo, 2);
        sHi += __shfl_xor_sync(0xFFFFFFFFu, sHi, 1);
        sHi += __shfl_xor_sync(0xFFFFFFFFu, sHi, 2);
        if ((lid & 3) == 0) {
            rowsum2[lr][wn]     = sLo;
            rowsum2[lr + 8][wn] = sHi;
        }
    }
    __syncthreads();
    if (tid < 128) {
        float s = rowsum2[tid][0] + rowsum2[tid][1] + rowsum2[tid][2] + rowsum2[tid][3];
        g_partial[(size_t)(bt0 + tid) * NVB + blockIdx.x] = s;
    }
}

// ---------------- kernel 5: logZ per row (reduce 250 partials) ---------------
__global__ void __launch_bounds__(256) k_logz() {
    __shared__ float red[8];
    int bt = blockIdx.x, tid = threadIdx.x;
    float s = (tid < NVB) ? g_partial[(size_t)bt * NVB + tid] : 0.f;
    #pragma unroll
    for (int o = 16; o; o >>= 1) s += __shfl_xor_sync(0xFFFFFFFFu, s, o);
    if ((tid & 31) == 0) red[tid >> 5] = s;
    __syncthreads();
    if (tid < 32) {
        float t = (tid < 8) ? red[tid] : 0.f;
        #pragma unroll
        for (int o = 4; o; o >>= 1) t += __shfl_xor_sync(0xFFFFFFFFu, t, o);
        if (tid == 0) g_logz[bt] = logf(t);
    }
}

// ---------------- kernel 6: out[bt, :] -= logz[bt] (pure streaming) ----------
__global__ void __launch_bounds__(256) k_sub(float* __restrict__ out) {
    int bt = blockIdx.y;
    int idx = blockIdx.x * 256 + threadIdx.x;
    if (idx * 4 >= VV) return;
    float z = g_logz[bt];
    float4* p = (float4*)(out + (size_t)bt * VV) + idx;
    float4 v = *p;
    v.x -= z; v.y -= z; v.z -= z; v.w -= z;
    *p = v;
}

// ---------------- launch ------------------------------------------------------
extern "C" void kernel_launch(void* const* d_in, const int* in_sizes, int n_in,
                              void* d_out, int out_size) {
    const float* enc_hid = (const float*)d_in[1];
    const int*   target  = (const int*)d_in[2];
    const float* emb     = (const float*)d_in[3];
    const float* W_ih    = (const float*)d_in[4];
    const float* W_hh    = (const float*)d_in[5];
    const float* b_ih    = (const float*)d_in[6];
    const float* b_hh    = (const float*)d_in[7];
    const float* W_out   = (const float*)d_in[8];
    const float* b_out   = (const float*)d_in[9];
    float* out    = (float*)d_out;
    float* h_last = out + (size_t)BB * TT * VV;

    cudaFuncSetAttribute(k_gemm, cudaFuncAttributeMaxDynamicSharedMemorySize, GEMM_DSM);

    k_nop<<<1, 32>>>();                       // keeps k_rnn at profiled launch #3
    k_wcvt<<<8000, 256>>>(W_out);
    k_xproj<<<128, 256>>>(target, emb, W_ih);
    k_rnn<<<128, 256>>>(enc_hid, W_hh, b_ih, b_hh, h_last);
    dim3 gg(VV / 128, (BB * TT) / 128);
    k_gemm<<<gg, 256, GEMM_DSM>>>(b_out, out);
    k_logz<<<BB * TT, 256>>>();
    dim3 gs((VV / 4 + 255) / 256, BB * TT);
    k_sub<<<gs, 256>>>(out);
}